// round 1
// baseline (speedup 1.0000x reference)
#include <cuda_runtime.h>
#include <math_constants.h>

#define NN  131072      // nodes = B*S
#define HH  128         // hidden
#define EE  1048576     // edges
#define BB  2048        // molecules
#define SS  64          // nodes per molecule
#define NF  74          // input node features
#define DFF 512         // ffn hidden
#define LG  4           // gine layers
#define LSS 2           // sab layers
#define NH  8           // heads
#define DH  16          // head dim

// ---------------- scratch (device globals; no allocation allowed) ----------
__device__ float g_h[NN * HH];       // node state
__device__ float g_z[NN * HH];       // pre-BN GINE output
__device__ float g_sum[HH];
__device__ float g_sumsq[HH];
__device__ float g_bn_a[HH];
__device__ float g_bn_c[HH];
__device__ int   g_cnt[BB];
__device__ int   g_fill[BB];
__device__ int   g_start[BB + 1];
__device__ int   g_order[EE];

// ---------------- helpers ---------------------------------------------------
// C[64][128] = act(A[64][K] @ Wsm[K][128] + bias), optional accumulate into C.
// blockDim.x must be 256. C stride is HH (may be global or smem).
__device__ __forceinline__ void cta_gemm(const float* __restrict__ A, int lda, int K,
                                         const float* __restrict__ Wsm,
                                         const float* __restrict__ bias,
                                         float* __restrict__ C,
                                         bool relu, bool accum)
{
    int tid = threadIdx.x;
    int ty = tid >> 4;          // 0..15 -> 4 rows each
    int tx = tid & 15;          // 0..15 -> 8 cols each
    int r0 = ty * 4;
    int c0 = tx * 8;
    float acc[4][8];
#pragma unroll
    for (int i = 0; i < 4; i++)
#pragma unroll
        for (int j = 0; j < 8; j++)
            acc[i][j] = accum ? C[(r0 + i) * HH + c0 + j] : 0.0f;

#pragma unroll 4
    for (int k = 0; k < K; k++) {
        float a0 = A[(r0 + 0) * lda + k];
        float a1 = A[(r0 + 1) * lda + k];
        float a2 = A[(r0 + 2) * lda + k];
        float a3 = A[(r0 + 3) * lda + k];
        const float4* wr = reinterpret_cast<const float4*>(&Wsm[k * HH + c0]);
        float4 w0 = wr[0];
        float4 w1 = wr[1];
        float w[8] = {w0.x, w0.y, w0.z, w0.w, w1.x, w1.y, w1.z, w1.w};
#pragma unroll
        for (int j = 0; j < 8; j++) {
            acc[0][j] = fmaf(a0, w[j], acc[0][j]);
            acc[1][j] = fmaf(a1, w[j], acc[1][j]);
            acc[2][j] = fmaf(a2, w[j], acc[2][j]);
            acc[3][j] = fmaf(a3, w[j], acc[3][j]);
        }
    }
    if (bias) {
#pragma unroll
        for (int j = 0; j < 8; j++) {
            float bj = bias[c0 + j];
#pragma unroll
            for (int i = 0; i < 4; i++) acc[i][j] += bj;
        }
    }
    if (relu) {
#pragma unroll
        for (int i = 0; i < 4; i++)
#pragma unroll
            for (int j = 0; j < 8; j++) acc[i][j] = fmaxf(acc[i][j], 0.0f);
    }
#pragma unroll
    for (int i = 0; i < 4; i++)
#pragma unroll
        for (int j = 0; j < 8; j++)
            C[(r0 + i) * HH + c0 + j] = acc[i][j];
}

__device__ __forceinline__ void load_w128(const float* __restrict__ g, float* __restrict__ wsm)
{
    const float4* g4 = reinterpret_cast<const float4*>(g);
    float4* s4 = reinterpret_cast<float4*>(wsm);
    for (int i = threadIdx.x; i < HH * HH / 4; i += blockDim.x) s4[i] = g4[i];
}

// wsm[k][0..127] = g[k*gstride + 0..127], k < K (gstride multiple of 4)
__device__ __forceinline__ void load_w_strided(const float* __restrict__ g, int gstride, int K,
                                               float* __restrict__ wsm)
{
    for (int i = threadIdx.x; i < K * (HH / 4); i += blockDim.x) {
        int k = i >> 5;
        int j4 = i & 31;
        reinterpret_cast<float4*>(wsm)[k * 32 + j4] =
            *reinterpret_cast<const float4*>(g + k * gstride + j4 * 4);
    }
}

// per-row layernorm over 64 rows of X[64][128] -> O, gamma/beta from global
__device__ __forceinline__ void ln_rows(const float* __restrict__ X, float* __restrict__ O,
                                        const float* __restrict__ gg, const float* __restrict__ bb)
{
    int wid = threadIdx.x >> 5;
    int lane = threadIdx.x & 31;
    for (int r = wid; r < SS; r += 8) {
        float v0 = X[r * HH + lane];
        float v1 = X[r * HH + lane + 32];
        float v2 = X[r * HH + lane + 64];
        float v3 = X[r * HH + lane + 96];
        float s = v0 + v1 + v2 + v3;
        float ss = v0 * v0 + v1 * v1 + v2 * v2 + v3 * v3;
#pragma unroll
        for (int o = 16; o; o >>= 1) {
            s += __shfl_xor_sync(0xffffffffu, s, o);
            ss += __shfl_xor_sync(0xffffffffu, ss, o);
        }
        float mu = s * (1.0f / HH);
        float var = ss * (1.0f / HH) - mu * mu;
        float inv = rsqrtf(var + 1e-5f);
        O[r * HH + lane]      = (v0 - mu) * inv * gg[lane]      + bb[lane];
        O[r * HH + lane + 32] = (v1 - mu) * inv * gg[lane + 32] + bb[lane + 32];
        O[r * HH + lane + 64] = (v2 - mu) * inv * gg[lane + 64] + bb[lane + 64];
        O[r * HH + lane + 96] = (v3 - mu) * inv * gg[lane + 96] + bb[lane + 96];
    }
}

// ---------------- edge bucketing --------------------------------------------
__global__ void zero_aux_kernel()
{
    int i = blockIdx.x * blockDim.x + threadIdx.x;
    if (i < BB) { g_cnt[i] = 0; g_fill[i] = 0; }
}

__global__ void edge_hist_kernel(const int* __restrict__ src)
{
    int e = blockIdx.x * blockDim.x + threadIdx.x;
    if (e < EE) atomicAdd(&g_cnt[src[e] >> 6], 1);
}

__global__ void scan_counts_kernel()
{
    __shared__ int ps[256];
    int tid = threadIdx.x;
    int local[8];
    int s = 0;
#pragma unroll
    for (int i = 0; i < 8; i++) { local[i] = g_cnt[tid * 8 + i]; s += local[i]; }
    ps[tid] = s;
    __syncthreads();
    for (int off = 1; off < 256; off <<= 1) {
        int v = (tid >= off) ? ps[tid - off] : 0;
        __syncthreads();
        ps[tid] += v;
        __syncthreads();
    }
    int run = ps[tid] - s;   // exclusive prefix
#pragma unroll
    for (int i = 0; i < 8; i++) { g_start[tid * 8 + i] = run; run += local[i]; }
    if (tid == 255) g_start[BB] = run;
}

__global__ void edge_scatter_kernel(const int* __restrict__ src)
{
    int e = blockIdx.x * blockDim.x + threadIdx.x;
    if (e < EE) {
        int m = src[e] >> 6;
        int p = atomicAdd(&g_fill[m], 1);
        g_order[g_start[m] + p] = e;
    }
}

// ---------------- input projection ------------------------------------------
__global__ void input_proj_kernel(const float* __restrict__ nf,
                                  const float* __restrict__ Win,
                                  const float* __restrict__ bin)
{
    extern __shared__ float smem[];
    float* asm_ = smem;            // 64 x 74
    float* wsm = smem + SS * NF;   // 74 x 128
    int m = blockIdx.x;
    int row0 = m * SS;
    for (int i = threadIdx.x; i < SS * NF; i += blockDim.x) asm_[i] = nf[row0 * NF + i];
    load_w_strided(Win, HH, NF, wsm);
    __syncthreads();
    cta_gemm(asm_, NF, NF, wsm, bin, g_h + row0 * HH, false, false);
}

// ---------------- GINE layer -------------------------------------------------
__global__ void gine_kernel(const float* __restrict__ ef,
                            const int* __restrict__ src,
                            const int* __restrict__ dst,
                            const float* __restrict__ We, const float* __restrict__ be,
                            const float* __restrict__ W1, const float* __restrict__ b1,
                            const float* __restrict__ W2, const float* __restrict__ b2)
{
    extern __shared__ float smem[];
    float* hb   = smem;                 // 64x128
    float* ag   = hb + SS * HH;         // 64x128 (agg -> z -> z2)
    float* z1   = ag + SS * HH;         // 64x128
    float* wsm  = z1 + SS * HH;         // 128x128
    float* wesm = wsm + HH * HH;        // 4x128
    float* besm = wesm + 4 * HH;        // 128
    int m = blockIdx.x;
    int row0 = m * SS;
    int tid = threadIdx.x;

    {
        float4* hb4 = reinterpret_cast<float4*>(hb);
        float4* ag4 = reinterpret_cast<float4*>(ag);
        const float4* gh4 = reinterpret_cast<const float4*>(g_h + row0 * HH);
        for (int i = tid; i < SS * HH / 4; i += 256) {
            hb4[i] = gh4[i];
            ag4[i] = make_float4(0.f, 0.f, 0.f, 0.f);
        }
        for (int i = tid; i < 4 * HH; i += 256) wesm[i] = We[i];
        if (tid < HH) besm[tid] = be[tid];
    }
    __syncthreads();

    // message passing: msg = relu(h[src] + e), scatter-add at dst
    {
        int ebeg = g_start[m], eend = g_start[m + 1];
        int wid = tid >> 5, lane = tid & 31;
        for (int idx = ebeg + wid; idx < eend; idx += 8) {
            int e = g_order[idx];
            int s = src[e] & (SS - 1);
            int d = dst[e] & (SS - 1);
            float4 f4 = reinterpret_cast<const float4*>(ef)[e];
#pragma unroll
            for (int q = 0; q < 4; q++) {
                int f = lane + q * 32;
                float msg = hb[s * HH + f]
                          + f4.x * wesm[f] + f4.y * wesm[HH + f]
                          + f4.z * wesm[2 * HH + f] + f4.w * wesm[3 * HH + f]
                          + besm[f];
                msg = fmaxf(msg, 0.0f);
                atomicAdd(&ag[d * HH + f], msg);
            }
        }
    }
    __syncthreads();
    for (int i = tid; i < SS * HH; i += 256) ag[i] += hb[i];   // z = h + agg
    __syncthreads();

    load_w128(W1, wsm);
    __syncthreads();
    cta_gemm(ag, HH, HH, wsm, b1, z1, true, false);            // z1 = relu(z@W1+b1)
    __syncthreads();
    load_w128(W2, wsm);
    __syncthreads();
    cta_gemm(z1, HH, HH, wsm, b2, ag, false, false);           // z2 = z1@W2+b2
    __syncthreads();

    if (tid < HH) {
        float s = 0.f, ss = 0.f;
        for (int r = 0; r < SS; r++) {
            float v = ag[r * HH + tid];
            s += v;
            ss += v * v;
        }
        atomicAdd(&g_sum[tid], s);
        atomicAdd(&g_sumsq[tid], ss);
    }
    {
        float4* gz4 = reinterpret_cast<float4*>(g_z + row0 * HH);
        const float4* ag4 = reinterpret_cast<const float4*>(ag);
        for (int i = tid; i < SS * HH / 4; i += 256) gz4[i] = ag4[i];
    }
}

__global__ void bn_finalize_kernel(const float* __restrict__ bng, const float* __restrict__ bnb)
{
    int f = threadIdx.x;
    float mu = g_sum[f] * (1.0f / NN);
    float var = g_sumsq[f] * (1.0f / NN) - mu * mu;
    float inv = rsqrtf(var + 1e-5f);
    float a = inv * bng[f];
    g_bn_a[f] = a;
    g_bn_c[f] = bnb[f] - mu * a;
    g_sum[f] = 0.0f;        // reset for next layer / next run
    g_sumsq[f] = 0.0f;
}

__global__ void bn_apply_kernel()
{
    int i = blockIdx.x * blockDim.x + threadIdx.x;       // float4 index
    if (i >= NN * HH / 4) return;
    int f0 = (i & (HH / 4 - 1)) * 4;
    float4 z = reinterpret_cast<const float4*>(g_z)[i];
    float4 h = reinterpret_cast<const float4*>(g_h)[i];
    float4 r;
    r.x = fmaxf(fmaf(z.x, g_bn_a[f0 + 0], g_bn_c[f0 + 0]), 0.f) + h.x;
    r.y = fmaxf(fmaf(z.y, g_bn_a[f0 + 1], g_bn_c[f0 + 1]), 0.f) + h.y;
    r.z = fmaxf(fmaf(z.z, g_bn_a[f0 + 2], g_bn_c[f0 + 2]), 0.f) + h.z;
    r.w = fmaxf(fmaf(z.w, g_bn_a[f0 + 3], g_bn_c[f0 + 3]), 0.f) + h.w;
    reinterpret_cast<float4*>(g_h)[i] = r;
}

// ---------------- SAB layer --------------------------------------------------
__global__ void sab_kernel(const float* __restrict__ Wq, const float* __restrict__ Wk,
                           const float* __restrict__ Wv, const float* __restrict__ Wo,
                           const float* __restrict__ W1, const float* __restrict__ b1,
                           const float* __restrict__ W2, const float* __restrict__ b2,
                           const float* __restrict__ l1g, const float* __restrict__ l1b,
                           const float* __restrict__ l2g, const float* __restrict__ l2b,
                           const int* __restrict__ lengths, float* __restrict__ out)
{
    extern __shared__ float smem[];
    float* xb  = smem;
    float* qb  = xb + SS * HH;
    float* kb  = qb + SS * HH;
    float* vb  = kb + SS * HH;
    float* wsm = vb + SS * HH;    // 128x128, also aliased as score scratch (64x65)
    float* scr = wsm;
    int m = blockIdx.x;
    int row0 = m * SS;
    int tid = threadIdx.x;

    {
        const float4* gx4 = reinterpret_cast<const float4*>(g_h + row0 * HH);
        float4* xb4 = reinterpret_cast<float4*>(xb);
        for (int i = tid; i < SS * HH / 4; i += 256) xb4[i] = gx4[i];
    }
    __syncthreads();
    ln_rows(xb, vb, l1g, l1b);                 // xn -> vb (temp)
    __syncthreads();
    load_w128(Wq, wsm); __syncthreads();
    cta_gemm(vb, HH, HH, wsm, nullptr, qb, false, false); __syncthreads();
    load_w128(Wk, wsm); __syncthreads();
    cta_gemm(xb, HH, HH, wsm, nullptr, kb, false, false); __syncthreads();
    load_w128(Wv, wsm); __syncthreads();
    cta_gemm(xb, HH, HH, wsm, nullptr, vb, false, false); __syncthreads();

    int len = lengths[m];
    const float scale = 0.25f;                  // 1/sqrt(16)
    for (int hh = 0; hh < NH; hh++) {
        {   // scores
            int i = tid >> 2;
            int j0 = (tid & 3) * 16;
            float qreg[DH];
#pragma unroll
            for (int d = 0; d < DH; d++) qreg[d] = qb[i * HH + hh * DH + d];
#pragma unroll
            for (int jj = 0; jj < 16; jj++) {
                int j = j0 + jj;
                float sdot = 0.f;
#pragma unroll
                for (int d = 0; d < DH; d++) sdot += qreg[d] * kb[j * HH + hh * DH + d];
                scr[i * 65 + j] = (i < len && j < len) ? sdot * scale : -CUDART_INF_F;
            }
        }
        __syncthreads();
        {   // softmax rows
            int wid = tid >> 5, lane = tid & 31;
            for (int r = wid; r < SS; r += 8) {
                float x0 = scr[r * 65 + lane];
                float x1 = scr[r * 65 + lane + 32];
                float mx = fmaxf(x0, x1);
#pragma unroll
                for (int o = 16; o; o >>= 1) mx = fmaxf(mx, __shfl_xor_sync(0xffffffffu, mx, o));
                float e0 = (r < len && lane < len)      ? __expf(x0 - mx) : 0.f;
                float e1 = (r < len && lane + 32 < len) ? __expf(x1 - mx) : 0.f;
                float sm = e0 + e1;
#pragma unroll
                for (int o = 16; o; o >>= 1) sm += __shfl_xor_sync(0xffffffffu, sm, o);
                float rinv = (sm > 0.f) ? (1.0f / sm) : 0.f;
                scr[r * 65 + lane]      = e0 * rinv;
                scr[r * 65 + lane + 32] = e1 * rinv;
            }
        }
        __syncthreads();
        {   // att_h = alpha @ v_h, overwrite dead q_h columns
            int i2 = tid >> 2;
            int d0 = (tid & 3) * 4;
            float a0 = 0.f, a1 = 0.f, a2 = 0.f, a3 = 0.f;
#pragma unroll 8
            for (int j = 0; j < SS; j++) {
                float al = scr[i2 * 65 + j];
                const float* vr = &vb[j * HH + hh * DH + d0];
                a0 = fmaf(al, vr[0], a0);
                a1 = fmaf(al, vr[1], a1);
                a2 = fmaf(al, vr[2], a2);
                a3 = fmaf(al, vr[3], a3);
            }
            float* qr = &qb[i2 * HH + hh * DH + d0];
            qr[0] = a0; qr[1] = a1; qr[2] = a2; qr[3] = a3;
        }
        __syncthreads();
    }

    load_w128(Wo, wsm); __syncthreads();
    cta_gemm(qb, HH, HH, wsm, nullptr, xb, false, true);   // x += att @ Wo
    __syncthreads();
    ln_rows(xb, kb, l2g, l2b);                             // xn2 -> kb
    __syncthreads();

    for (int c = 0; c < 4; c++) {                          // fused FFN, 128-col chunks
        load_w_strided(W1 + c * HH, DFF, HH, wsm); __syncthreads();
        cta_gemm(kb, HH, HH, wsm, b1 + c * HH, qb, true, false); __syncthreads();
        load_w128(W2 + c * HH * HH, wsm); __syncthreads();
        cta_gemm(qb, HH, HH, wsm, (c == 0) ? b2 : nullptr, xb, false, true); __syncthreads();
    }

    float* op = out ? out : g_h;
    {
        float4* o4 = reinterpret_cast<float4*>(op + row0 * HH);
        const float4* xb4 = reinterpret_cast<const float4*>(xb);
        for (int i = tid; i < SS * HH / 4; i += 256) o4[i] = xb4[i];
    }
}

// ---------------- launch ------------------------------------------------------
extern "C" void kernel_launch(void* const* d_in, const int* in_sizes, int n_in,
                              void* d_out, int out_size)
{
    const float* node_feat = (const float*)d_in[0];
    const float* edge_feat = (const float*)d_in[1];
    const float* W_in   = (const float*)d_in[2];
    const float* b_in   = (const float*)d_in[3];
    const float* W_e    = (const float*)d_in[4];
    const float* b_e    = (const float*)d_in[5];
    const float* gW1    = (const float*)d_in[6];
    const float* gb1    = (const float*)d_in[7];
    const float* gW2    = (const float*)d_in[8];
    const float* gb2    = (const float*)d_in[9];
    const float* bn_g   = (const float*)d_in[10];
    const float* bn_b   = (const float*)d_in[11];
    const float* Wq     = (const float*)d_in[12];
    const float* Wk     = (const float*)d_in[13];
    const float* Wv     = (const float*)d_in[14];
    const float* Wo     = (const float*)d_in[15];
    const float* fW1    = (const float*)d_in[16];
    const float* fb1    = (const float*)d_in[17];
    const float* fW2    = (const float*)d_in[18];
    const float* fb2    = (const float*)d_in[19];
    const float* l1g    = (const float*)d_in[20];
    const float* l1b    = (const float*)d_in[21];
    const float* l2g    = (const float*)d_in[22];
    const float* l2b    = (const float*)d_in[23];
    const int*   src    = (const int*)d_in[24];
    const int*   dst    = (const int*)d_in[25];
    const int*   lengths= (const int*)d_in[26];

    const int IN_SMEM   = (SS * NF + NF * HH) * 4;
    const int GINE_SMEM = (3 * SS * HH + HH * HH + 4 * HH + HH) * 4;
    const int SAB_SMEM  = (4 * SS * HH + HH * HH) * 4;

    cudaFuncSetAttribute(input_proj_kernel, cudaFuncAttributeMaxDynamicSharedMemorySize, IN_SMEM);
    cudaFuncSetAttribute(gine_kernel, cudaFuncAttributeMaxDynamicSharedMemorySize, GINE_SMEM);
    cudaFuncSetAttribute(sab_kernel, cudaFuncAttributeMaxDynamicSharedMemorySize, SAB_SMEM);

    // bucket edges by molecule (src and dst are always in the same molecule)
    zero_aux_kernel<<<(BB + 255) / 256, 256>>>();
    edge_hist_kernel<<<EE / 256, 256>>>(src);
    scan_counts_kernel<<<1, 256>>>();
    edge_scatter_kernel<<<EE / 256, 256>>>(src);

    input_proj_kernel<<<BB, 256, IN_SMEM>>>(node_feat, W_in, b_in);

    for (int l = 0; l < LG; l++) {
        gine_kernel<<<BB, 256, GINE_SMEM>>>(edge_feat, src, dst, W_e, b_e,
                                            gW1 + l * HH * HH, gb1 + l * HH,
                                            gW2 + l * HH * HH, gb2 + l * HH);
        bn_finalize_kernel<<<1, HH>>>(bn_g + l * HH, bn_b + l * HH);
        bn_apply_kernel<<<(NN * HH / 4) / 256, 256>>>();
    }

    for (int l = 0; l < LSS; l++) {
        sab_kernel<<<BB, 256, SAB_SMEM>>>(Wq + l * HH * HH, Wk + l * HH * HH,
                                          Wv + l * HH * HH, Wo + l * HH * HH,
                                          fW1 + l * HH * DFF, fb1 + l * DFF,
                                          fW2 + l * DFF * HH, fb2 + l * HH,
                                          l1g + l * HH, l1b + l * HH,
                                          l2g + l * HH, l2b + l * HH,
                                          lengths,
                                          (l == LSS - 1) ? (float*)d_out : nullptr);
    }
}

// round 2
// speedup vs baseline: 1.1316x; 1.1316x over previous
#include <cuda_runtime.h>
#include <math_constants.h>

#define NN  131072      // nodes = B*S
#define HH  128         // hidden
#define EE  1048576     // edges
#define BB  2048        // molecules
#define SS  64          // nodes per molecule
#define NF  74          // input node features
#define DFF 512         // ffn hidden
#define LG  4           // gine layers
#define LSS 2           // sab layers
#define NH  8           // heads
#define DH  16          // head dim

typedef unsigned long long ull;

// packed fp32x2 helpers (sm_103a FFMA2)
#define PACK2(out, a)  asm("mov.b64 %0, {%1, %1};" : "=l"(out) : "r"(__float_as_uint(a)))
#define FFMA2(acc, a, b) asm("fma.rn.f32x2 %0, %1, %2, %0;" : "+l"(acc) : "l"(a), "l"(b))
#define UNPK2(lo, hi, in) do { unsigned _l, _h; \
    asm("mov.b64 {%0, %1}, %2;" : "=r"(_l), "=r"(_h) : "l"(in)); \
    lo = __uint_as_float(_l); hi = __uint_as_float(_h); } while (0)

// ---------------- scratch (device globals; no allocation allowed) ----------
__device__ __align__(16) float g_h[NN * HH];   // node state
__device__ __align__(16) float g_z[NN * HH];   // pre-BN GINE output
__device__ __align__(16) float g_sum[HH];
__device__ __align__(16) float g_sumsq[HH];
__device__ __align__(16) float g_bn_a[HH];
__device__ __align__(16) float g_bn_c[HH];
__device__ int g_cnt[BB];
__device__ int g_fill[BB];
__device__ int g_start[BB + 1];
__device__ int g_order[EE];      // sorted by molecule
__device__ int g_order2[EE];     // sorted by (molecule, dst)
__device__ int g_dstart[BB * 65];

// ---------------- helpers ---------------------------------------------------
// C[64][128] = act(A[64][K] @ Wsm[K][128] + bias), optional accumulate into C.
// blockDim.x must be 256. C stride is HH. Uses packed f32x2 FMA (exact fp32).
__device__ __forceinline__ void cta_gemm(const float* __restrict__ A, int lda, int K,
                                         const float* __restrict__ Wsm,
                                         const float* __restrict__ bias,
                                         float* __restrict__ C,
                                         bool relu, bool accum)
{
    int tid = threadIdx.x;
    int r0 = (tid >> 4) * 4;
    int c0 = (tid & 15) * 8;
    ull acc[4][4];
#pragma unroll
    for (int i = 0; i < 4; i++)
#pragma unroll
        for (int j = 0; j < 4; j++)
            acc[i][j] = accum ? *reinterpret_cast<const ull*>(&C[(r0 + i) * HH + c0 + 2 * j])
                              : 0ULL;

#pragma unroll 2
    for (int k = 0; k < K; k++) {
        ull a64[4];
#pragma unroll
        for (int i = 0; i < 4; i++) {
            float a = A[(r0 + i) * lda + k];
            PACK2(a64[i], a);
        }
        const ull* wr = reinterpret_cast<const ull*>(&Wsm[k * HH + c0]);
        ull w0 = wr[0], w1 = wr[1], w2 = wr[2], w3 = wr[3];
#pragma unroll
        for (int i = 0; i < 4; i++) {
            FFMA2(acc[i][0], a64[i], w0);
            FFMA2(acc[i][1], a64[i], w1);
            FFMA2(acc[i][2], a64[i], w2);
            FFMA2(acc[i][3], a64[i], w3);
        }
    }
#pragma unroll
    for (int i = 0; i < 4; i++)
#pragma unroll
        for (int j = 0; j < 4; j++) {
            float lo, hi;
            UNPK2(lo, hi, acc[i][j]);
            if (bias) { lo += bias[c0 + 2 * j]; hi += bias[c0 + 2 * j + 1]; }
            if (relu) { lo = fmaxf(lo, 0.f); hi = fmaxf(hi, 0.f); }
            C[(r0 + i) * HH + c0 + 2 * j]     = lo;
            C[(r0 + i) * HH + c0 + 2 * j + 1] = hi;
        }
}

__device__ __forceinline__ void load_w128(const float* __restrict__ g, float* __restrict__ wsm)
{
    const float4* g4 = reinterpret_cast<const float4*>(g);
    float4* s4 = reinterpret_cast<float4*>(wsm);
    for (int i = threadIdx.x; i < HH * HH / 4; i += blockDim.x) s4[i] = g4[i];
}

__device__ __forceinline__ void load_w_strided(const float* __restrict__ g, int gstride, int K,
                                               float* __restrict__ wsm)
{
    for (int i = threadIdx.x; i < K * (HH / 4); i += blockDim.x) {
        int k = i >> 5;
        int j4 = i & 31;
        reinterpret_cast<float4*>(wsm)[k * 32 + j4] =
            *reinterpret_cast<const float4*>(g + k * gstride + j4 * 4);
    }
}

__device__ __forceinline__ void ln_rows(const float* __restrict__ X, float* __restrict__ O,
                                        const float* __restrict__ gg, const float* __restrict__ bb)
{
    int wid = threadIdx.x >> 5;
    int lane = threadIdx.x & 31;
    for (int r = wid; r < SS; r += 8) {
        float v0 = X[r * HH + lane];
        float v1 = X[r * HH + lane + 32];
        float v2 = X[r * HH + lane + 64];
        float v3 = X[r * HH + lane + 96];
        float s = v0 + v1 + v2 + v3;
        float ss = v0 * v0 + v1 * v1 + v2 * v2 + v3 * v3;
#pragma unroll
        for (int o = 16; o; o >>= 1) {
            s += __shfl_xor_sync(0xffffffffu, s, o);
            ss += __shfl_xor_sync(0xffffffffu, ss, o);
        }
        float mu = s * (1.0f / HH);
        float var = ss * (1.0f / HH) - mu * mu;
        float inv = rsqrtf(var + 1e-5f);
        O[r * HH + lane]      = (v0 - mu) * inv * gg[lane]      + bb[lane];
        O[r * HH + lane + 32] = (v1 - mu) * inv * gg[lane + 32] + bb[lane + 32];
        O[r * HH + lane + 64] = (v2 - mu) * inv * gg[lane + 64] + bb[lane + 64];
        O[r * HH + lane + 96] = (v3 - mu) * inv * gg[lane + 96] + bb[lane + 96];
    }
}

// ---------------- edge bucketing --------------------------------------------
__global__ void zero_aux_kernel()
{
    int i = blockIdx.x * blockDim.x + threadIdx.x;
    if (i < BB) { g_cnt[i] = 0; g_fill[i] = 0; }
}

__global__ void edge_hist_kernel(const int* __restrict__ src)
{
    int e = blockIdx.x * blockDim.x + threadIdx.x;
    if (e < EE) atomicAdd(&g_cnt[src[e] >> 6], 1);
}

__global__ void scan_counts_kernel()
{
    __shared__ int ps[256];
    int tid = threadIdx.x;
    int local[8];
    int s = 0;
#pragma unroll
    for (int i = 0; i < 8; i++) { local[i] = g_cnt[tid * 8 + i]; s += local[i]; }
    ps[tid] = s;
    __syncthreads();
    for (int off = 1; off < 256; off <<= 1) {
        int v = (tid >= off) ? ps[tid - off] : 0;
        __syncthreads();
        ps[tid] += v;
        __syncthreads();
    }
    int run = ps[tid] - s;
#pragma unroll
    for (int i = 0; i < 8; i++) { g_start[tid * 8 + i] = run; run += local[i]; }
    if (tid == 255) g_start[BB] = run;
}

__global__ void edge_scatter_kernel(const int* __restrict__ src)
{
    int e = blockIdx.x * blockDim.x + threadIdx.x;
    if (e < EE) {
        int m = src[e] >> 6;
        int p = atomicAdd(&g_fill[m], 1);
        g_order[g_start[m] + p] = e;
    }
}

// sort each molecule's edges by dst (counting sort); record per-dst offsets
__global__ void edge_sort_dst_kernel(const int* __restrict__ dst)
{
    __shared__ int cnt[64];
    __shared__ int off[65];
    int m = blockIdx.x;
    int tid = threadIdx.x;
    int ebeg = g_start[m];
    int ne = g_start[m + 1] - ebeg;
    if (tid < 64) cnt[tid] = 0;
    __syncthreads();
    for (int i = tid; i < ne; i += 256)
        atomicAdd(&cnt[dst[g_order[ebeg + i]] & (SS - 1)], 1);
    __syncthreads();
    if (tid == 0) {
        int run = 0;
        for (int d = 0; d < 64; d++) { off[d] = run; run += cnt[d]; }
        off[64] = run;
    }
    __syncthreads();
    if (tid < 65) g_dstart[m * 65 + tid] = off[tid];
    if (tid < 64) cnt[tid] = off[tid];
    __syncthreads();
    for (int i = tid; i < ne; i += 256) {
        int e = g_order[ebeg + i];
        int d = dst[e] & (SS - 1);
        int p = atomicAdd(&cnt[d], 1);
        g_order2[ebeg + p] = e;
    }
}

// ---------------- input projection ------------------------------------------
__global__ void input_proj_kernel(const float* __restrict__ nf,
                                  const float* __restrict__ Win,
                                  const float* __restrict__ bin)
{
    extern __shared__ float smem[];
    float* asm_ = smem;
    float* wsm = smem + SS * NF;
    int m = blockIdx.x;
    int row0 = m * SS;
    for (int i = threadIdx.x; i < SS * NF; i += blockDim.x) asm_[i] = nf[row0 * NF + i];
    load_w_strided(Win, HH, NF, wsm);
    __syncthreads();
    cta_gemm(asm_, NF, NF, wsm, bin, g_h + row0 * HH, false, false);
}

// ---------------- GINE layer -------------------------------------------------
__global__ void gine_kernel(const float* __restrict__ ef,
                            const int* __restrict__ src,
                            const float* __restrict__ We, const float* __restrict__ be,
                            const float* __restrict__ W1, const float* __restrict__ b1,
                            const float* __restrict__ W2, const float* __restrict__ b2,
                            int fuse_bn)
{
    extern __shared__ float smem[];
    float* hb   = smem;                 // 64x128 (h input)
    float* ag   = hb + SS * HH;         // 64x128 (z = h+agg -> z2)
    float* z1   = ag + SS * HH;         // 64x128
    float* wsm  = z1 + SS * HH;         // 128x128
    float* wesm = wsm + HH * HH;        // 4x128
    float* besm = wesm + 4 * HH;        // 128
    int m = blockIdx.x;
    int row0 = m * SS;
    int tid = threadIdx.x;

    {
        float4* hb4 = reinterpret_cast<float4*>(hb);
        float4* gh4 = reinterpret_cast<float4*>(g_h + row0 * HH);
        if (fuse_bn) {
            const float4* gz4 = reinterpret_cast<const float4*>(g_z + row0 * HH);
            for (int i = tid; i < SS * HH / 4; i += 256) {
                int f0 = (i & 31) * 4;
                float4 a = *reinterpret_cast<const float4*>(&g_bn_a[f0]);
                float4 c = *reinterpret_cast<const float4*>(&g_bn_c[f0]);
                float4 z = gz4[i];
                float4 h = gh4[i];
                float4 r;
                r.x = fmaxf(fmaf(z.x, a.x, c.x), 0.f) + h.x;
                r.y = fmaxf(fmaf(z.y, a.y, c.y), 0.f) + h.y;
                r.z = fmaxf(fmaf(z.z, a.z, c.z), 0.f) + h.z;
                r.w = fmaxf(fmaf(z.w, a.w, c.w), 0.f) + h.w;
                hb4[i] = r;
                gh4[i] = r;   // persist h for next layer's residual
            }
        } else {
            for (int i = tid; i < SS * HH / 4; i += 256) hb4[i] = gh4[i];
        }
        for (int i = tid; i < 4 * HH; i += 256) wesm[i] = We[i];
        if (tid < HH) besm[tid] = be[tid];
    }
    __syncthreads();

    // message passing, atomic-free: warp owns dst rows, edges pre-sorted by dst
    {
        int ebeg = g_start[m];
        const int* gd = g_dstart + m * 65;
        int wid = tid >> 5, lane = tid & 31;
        for (int d = wid; d < SS; d += 8) {
            float a0 = 0.f, a1 = 0.f, a2 = 0.f, a3 = 0.f;
            int b = gd[d], en = gd[d + 1];
            for (int idx = b; idx < en; idx++) {
                int e = g_order2[ebeg + idx];
                int s = src[e] & (SS - 1);
                float4 f4 = reinterpret_cast<const float4*>(ef)[e];
                const float* hr = &hb[s * HH];
                {
                    int f = lane;
                    float msg = hr[f] + f4.x * wesm[f] + f4.y * wesm[HH + f]
                              + f4.z * wesm[2 * HH + f] + f4.w * wesm[3 * HH + f] + besm[f];
                    a0 += fmaxf(msg, 0.f);
                }
                {
                    int f = lane + 32;
                    float msg = hr[f] + f4.x * wesm[f] + f4.y * wesm[HH + f]
                              + f4.z * wesm[2 * HH + f] + f4.w * wesm[3 * HH + f] + besm[f];
                    a1 += fmaxf(msg, 0.f);
                }
                {
                    int f = lane + 64;
                    float msg = hr[f] + f4.x * wesm[f] + f4.y * wesm[HH + f]
                              + f4.z * wesm[2 * HH + f] + f4.w * wesm[3 * HH + f] + besm[f];
                    a2 += fmaxf(msg, 0.f);
                }
                {
                    int f = lane + 96;
                    float msg = hr[f] + f4.x * wesm[f] + f4.y * wesm[HH + f]
                              + f4.z * wesm[2 * HH + f] + f4.w * wesm[3 * HH + f] + besm[f];
                    a3 += fmaxf(msg, 0.f);
                }
            }
            // z = h + agg, written directly
            ag[d * HH + lane]      = a0 + hb[d * HH + lane];
            ag[d * HH + lane + 32] = a1 + hb[d * HH + lane + 32];
            ag[d * HH + lane + 64] = a2 + hb[d * HH + lane + 64];
            ag[d * HH + lane + 96] = a3 + hb[d * HH + lane + 96];
        }
    }
    load_w128(W1, wsm);
    __syncthreads();
    cta_gemm(ag, HH, HH, wsm, b1, z1, true, false);            // z1 = relu(z@W1+b1)
    __syncthreads();
    load_w128(W2, wsm);
    __syncthreads();
    cta_gemm(z1, HH, HH, wsm, b2, ag, false, false);           // z2 = z1@W2+b2
    __syncthreads();

    if (tid < HH) {
        float s = 0.f, ss = 0.f;
        for (int r = 0; r < SS; r++) {
            float v = ag[r * HH + tid];
            s += v;
            ss += v * v;
        }
        atomicAdd(&g_sum[tid], s);
        atomicAdd(&g_sumsq[tid], ss);
    }
    {
        float4* gz4 = reinterpret_cast<float4*>(g_z + row0 * HH);
        const float4* ag4 = reinterpret_cast<const float4*>(ag);
        for (int i = tid; i < SS * HH / 4; i += 256) gz4[i] = ag4[i];
    }
}

__global__ void bn_finalize_kernel(const float* __restrict__ bng, const float* __restrict__ bnb)
{
    int f = threadIdx.x;
    float mu = g_sum[f] * (1.0f / NN);
    float var = g_sumsq[f] * (1.0f / NN) - mu * mu;
    float inv = rsqrtf(var + 1e-5f);
    float a = inv * bng[f];
    g_bn_a[f] = a;
    g_bn_c[f] = bnb[f] - mu * a;
    g_sum[f] = 0.0f;
    g_sumsq[f] = 0.0f;
}

// ---------------- SAB layer --------------------------------------------------
__global__ void sab_kernel(const float* __restrict__ Wq, const float* __restrict__ Wk,
                           const float* __restrict__ Wv, const float* __restrict__ Wo,
                           const float* __restrict__ W1, const float* __restrict__ b1,
                           const float* __restrict__ W2, const float* __restrict__ b2,
                           const float* __restrict__ l1g, const float* __restrict__ l1b,
                           const float* __restrict__ l2g, const float* __restrict__ l2b,
                           const int* __restrict__ lengths, float* __restrict__ out,
                           int fuse_bn)
{
    extern __shared__ float smem[];
    float* xb  = smem;
    float* qb  = xb + SS * HH;
    float* kb  = qb + SS * HH;
    float* vb  = kb + SS * HH;
    float* wsm = vb + SS * HH;    // 128x128, aliased as score scratch (64x65)
    float* scr = wsm;
    int m = blockIdx.x;
    int row0 = m * SS;
    int tid = threadIdx.x;

    {
        float4* xb4 = reinterpret_cast<float4*>(xb);
        const float4* gx4 = reinterpret_cast<const float4*>(g_h + row0 * HH);
        if (fuse_bn) {
            const float4* gz4 = reinterpret_cast<const float4*>(g_z + row0 * HH);
            for (int i = tid; i < SS * HH / 4; i += 256) {
                int f0 = (i & 31) * 4;
                float4 a = *reinterpret_cast<const float4*>(&g_bn_a[f0]);
                float4 c = *reinterpret_cast<const float4*>(&g_bn_c[f0]);
                float4 z = gz4[i];
                float4 h = gx4[i];
                float4 r;
                r.x = fmaxf(fmaf(z.x, a.x, c.x), 0.f) + h.x;
                r.y = fmaxf(fmaf(z.y, a.y, c.y), 0.f) + h.y;
                r.z = fmaxf(fmaf(z.z, a.z, c.z), 0.f) + h.z;
                r.w = fmaxf(fmaf(z.w, a.w, c.w), 0.f) + h.w;
                xb4[i] = r;
            }
        } else {
            for (int i = tid; i < SS * HH / 4; i += 256) xb4[i] = gx4[i];
        }
    }
    __syncthreads();
    ln_rows(xb, vb, l1g, l1b);                 // xn -> vb (temp)
    __syncthreads();
    load_w128(Wq, wsm); __syncthreads();
    cta_gemm(vb, HH, HH, wsm, nullptr, qb, false, false); __syncthreads();
    load_w128(Wk, wsm); __syncthreads();
    cta_gemm(xb, HH, HH, wsm, nullptr, kb, false, false); __syncthreads();
    load_w128(Wv, wsm); __syncthreads();
    cta_gemm(xb, HH, HH, wsm, nullptr, vb, false, false); __syncthreads();

    int len = lengths[m];
    const float scale = 0.25f;                  // 1/sqrt(16)
    for (int hh = 0; hh < NH; hh++) {
        {   // scores (packed f32x2 over d)
            int i = tid >> 2;
            int j0 = (tid & 3) * 16;
            ull q2[8];
            const ull* qrow = reinterpret_cast<const ull*>(&qb[i * HH + hh * DH]);
#pragma unroll
            for (int d2 = 0; d2 < 8; d2++) q2[d2] = qrow[d2];
#pragma unroll
            for (int jj = 0; jj < 16; jj++) {
                int j = j0 + jj;
                const ull* krow = reinterpret_cast<const ull*>(&kb[j * HH + hh * DH]);
                ull s2 = 0ULL;
#pragma unroll
                for (int d2 = 0; d2 < 8; d2++) FFMA2(s2, q2[d2], krow[d2]);
                float lo, hi;
                UNPK2(lo, hi, s2);
                float sdot = lo + hi;
                scr[i * 65 + j] = (i < len && j < len) ? sdot * scale : -CUDART_INF_F;
            }
        }
        __syncthreads();
        {   // softmax rows
            int wid = tid >> 5, lane = tid & 31;
            for (int r = wid; r < SS; r += 8) {
                float x0 = scr[r * 65 + lane];
                float x1 = scr[r * 65 + lane + 32];
                float mx = fmaxf(x0, x1);
#pragma unroll
                for (int o = 16; o; o >>= 1) mx = fmaxf(mx, __shfl_xor_sync(0xffffffffu, mx, o));
                float e0 = (r < len && lane < len)      ? __expf(x0 - mx) : 0.f;
                float e1 = (r < len && lane + 32 < len) ? __expf(x1 - mx) : 0.f;
                float sm = e0 + e1;
#pragma unroll
                for (int o = 16; o; o >>= 1) sm += __shfl_xor_sync(0xffffffffu, sm, o);
                float rinv = (sm > 0.f) ? (1.0f / sm) : 0.f;
                scr[r * 65 + lane]      = e0 * rinv;
                scr[r * 65 + lane + 32] = e1 * rinv;
            }
        }
        __syncthreads();
        {   // att_h = alpha @ v_h (packed), overwrite dead q_h columns
            int i2 = tid >> 2;
            int d0 = (tid & 3) * 4;
            ull acc0 = 0ULL, acc1 = 0ULL;
#pragma unroll 8
            for (int j = 0; j < SS; j++) {
                float al = scr[i2 * 65 + j];
                ull al2;
                PACK2(al2, al);
                const ull* vr = reinterpret_cast<const ull*>(&vb[j * HH + hh * DH + d0]);
                FFMA2(acc0, al2, vr[0]);
                FFMA2(acc1, al2, vr[1]);
            }
            float* qr = &qb[i2 * HH + hh * DH + d0];
            float lo, hi;
            UNPK2(lo, hi, acc0); qr[0] = lo; qr[1] = hi;
            UNPK2(lo, hi, acc1); qr[2] = lo; qr[3] = hi;
        }
        __syncthreads();
    }

    load_w128(Wo, wsm); __syncthreads();
    cta_gemm(qb, HH, HH, wsm, nullptr, xb, false, true);   // x += att @ Wo
    __syncthreads();
    ln_rows(xb, kb, l2g, l2b);                             // xn2 -> kb
    __syncthreads();

    for (int c = 0; c < 4; c++) {                          // fused FFN, 128-col chunks
        load_w_strided(W1 + c * HH, DFF, HH, wsm); __syncthreads();
        cta_gemm(kb, HH, HH, wsm, b1 + c * HH, qb, true, false); __syncthreads();
        load_w128(W2 + c * HH * HH, wsm); __syncthreads();
        cta_gemm(qb, HH, HH, wsm, (c == 0) ? b2 : nullptr, xb, false, true); __syncthreads();
    }

    float* op = out ? out : g_h;
    {
        float4* o4 = reinterpret_cast<float4*>(op + row0 * HH);
        const float4* xb4 = reinterpret_cast<const float4*>(xb);
        for (int i = tid; i < SS * HH / 4; i += 256) o4[i] = xb4[i];
    }
}

// ---------------- launch ------------------------------------------------------
extern "C" void kernel_launch(void* const* d_in, const int* in_sizes, int n_in,
                              void* d_out, int out_size)
{
    const float* node_feat = (const float*)d_in[0];
    const float* edge_feat = (const float*)d_in[1];
    const float* W_in   = (const float*)d_in[2];
    const float* b_in   = (const float*)d_in[3];
    const float* W_e    = (const float*)d_in[4];
    const float* b_e    = (const float*)d_in[5];
    const float* gW1    = (const float*)d_in[6];
    const float* gb1    = (const float*)d_in[7];
    const float* gW2    = (const float*)d_in[8];
    const float* gb2    = (const float*)d_in[9];
    const float* bn_g   = (const float*)d_in[10];
    const float* bn_b   = (const float*)d_in[11];
    const float* Wq     = (const float*)d_in[12];
    const float* Wk     = (const float*)d_in[13];
    const float* Wv     = (const float*)d_in[14];
    const float* Wo     = (const float*)d_in[15];
    const float* fW1    = (const float*)d_in[16];
    const float* fb1    = (const float*)d_in[17];
    const float* fW2    = (const float*)d_in[18];
    const float* fb2    = (const float*)d_in[19];
    const float* l1g    = (const float*)d_in[20];
    const float* l1b    = (const float*)d_in[21];
    const float* l2g    = (const float*)d_in[22];
    const float* l2b    = (const float*)d_in[23];
    const int*   src    = (const int*)d_in[24];
    const int*   dst    = (const int*)d_in[25];
    const int*   lengths= (const int*)d_in[26];

    const int IN_SMEM   = (SS * NF + NF * HH) * 4;
    const int GINE_SMEM = (3 * SS * HH + HH * HH + 4 * HH + HH) * 4;
    const int SAB_SMEM  = (4 * SS * HH + HH * HH) * 4;

    cudaFuncSetAttribute(input_proj_kernel, cudaFuncAttributeMaxDynamicSharedMemorySize, IN_SMEM);
    cudaFuncSetAttribute(gine_kernel, cudaFuncAttributeMaxDynamicSharedMemorySize, GINE_SMEM);
    cudaFuncSetAttribute(sab_kernel, cudaFuncAttributeMaxDynamicSharedMemorySize, SAB_SMEM);

    // bucket edges by molecule, then sort by dst within molecule
    zero_aux_kernel<<<(BB + 255) / 256, 256>>>();
    edge_hist_kernel<<<EE / 256, 256>>>(src);
    scan_counts_kernel<<<1, 256>>>();
    edge_scatter_kernel<<<EE / 256, 256>>>(src);
    edge_sort_dst_kernel<<<BB, 256>>>(dst);

    input_proj_kernel<<<BB, 256, IN_SMEM>>>(node_feat, W_in, b_in);

    for (int l = 0; l < LG; l++) {
        gine_kernel<<<BB, 256, GINE_SMEM>>>(edge_feat, src, W_e, b_e,
                                            gW1 + l * HH * HH, gb1 + l * HH,
                                            gW2 + l * HH * HH, gb2 + l * HH,
                                            l > 0 ? 1 : 0);
        bn_finalize_kernel<<<1, HH>>>(bn_g + l * HH, bn_b + l * HH);
    }

    for (int l = 0; l < LSS; l++) {
        sab_kernel<<<BB, 256, SAB_SMEM>>>(Wq + l * HH * HH, Wk + l * HH * HH,
                                          Wv + l * HH * HH, Wo + l * HH * HH,
                                          fW1 + l * HH * DFF, fb1 + l * DFF,
                                          fW2 + l * DFF * HH, fb2 + l * HH,
                                          l1g + l * HH, l1b + l * HH,
                                          l2g + l * HH, l2b + l * HH,
                                          lengths,
                                          (l == LSS - 1) ? (float*)d_out : nullptr,
                                          l == 0 ? 1 : 0);
    }
}